// round 15
// baseline (speedup 1.0000x reference)
#include <cuda_runtime.h>
#include <cuda_bf16.h>
#include <math_constants.h>
#include <cstdint>

#define BB 2
#define LL 384
#define DD 256
#define VV 32000
#define NLY 3
#define BL (BB*LL)
#define KP 768   // A split-K: [Ah|Al|Ah]; B stored dedup as [Wh|Wl] (512)

// ---------------- scratch (device globals; no allocation) ----------------
__device__ __align__(128) float g_real[BL*DD], g_imag[BL*DD];
__device__ __align__(128) float g_c[BL*DD], g_s[BL*DD];
__device__ __align__(128) float g_outr[BL*DD], g_outi[BL*DD];
__device__ __align__(128) float g_scp[BB*6*DD], g_ssp[BB*6*DD];
__device__ __align__(128) float g_wmean[NLY*DD];
__device__ __align__(128) float g_scores[BB*LL*LL];
__device__ __align__(128) __nv_bfloat16 g_cw[BL*512];            // [row][cw|sw]
__device__ __align__(128) __nv_bfloat16 g_cs[BL*512];            // [row][c|s]
__device__ __align__(128) __nv_bfloat16 g_nb[BL*512];            // [row][nr|ni]
__device__ __align__(128) __nv_bfloat16 g_nT[BB*512*LL];         // [b][d(512)][m]
__device__ __align__(128) __nv_bfloat16 g_attnb[BB*LL*LL];       // [row l][m]
__device__ __align__(128) __nv_bfloat16 g_aexp[BL*KP];
__device__ __align__(128) __nv_bfloat16 g_bt[(size_t)VV*512];    // [v][Wh|Wl] 32.8 MB

// chunk -> B k-offset/32 tables
__device__ const int g_tlin[24]   = {0,1,2,3,4,5,6,7,8,9,10,11,12,13,14,15,16,17,18,19,20,21,22,23};
__device__ const int g_tsplit[24] = {0,1,2,3,4,5,6,7, 0,1,2,3,4,5,6,7, 8,9,10,11,12,13,14,15};

// ---------------- helpers ----------------
__device__ __forceinline__ float clip1(float v) { return fminf(fmaxf(v, -1.f), 1.f); }
__device__ __forceinline__ float sigm(float v) { return 1.f / (1.f + expf(-v)); }

__device__ __forceinline__ void blockSum2(float a, float b, float* sh, float& oa, float& ob) {
    int lane = threadIdx.x & 31, w = threadIdx.x >> 5;
    #pragma unroll
    for (int o = 16; o; o >>= 1) {
        a += __shfl_xor_sync(0xffffffffu, a, o);
        b += __shfl_xor_sync(0xffffffffu, b, o);
    }
    __syncthreads();
    if (lane == 0) { sh[w] = a; sh[8 + w] = b; }
    __syncthreads();
    float sa = 0.f, sb = 0.f;
    #pragma unroll
    for (int i = 0; i < 8; i++) { sa += sh[i]; sb += sh[8 + i]; }
    oa = sa; ob = sb;
}

__device__ __forceinline__ uint32_t s2u(const void* p) {
    uint32_t a;
    asm("{ .reg .u64 t; cvta.to.shared.u64 t, %1; cvt.u32.u64 %0, t; }" : "=r"(a) : "l"(p));
    return a;
}
__device__ __forceinline__ void cpa16(uint32_t s, const void* g) {
    asm volatile("cp.async.cg.shared.global [%0], [%1], 16;" :: "r"(s), "l"(g));
}

// ---------------- shared bf16 HMMA mainloop, cp.async 3-stage pipeline ----------------
// CTA 128x128, 8 warps = 2(M) x 4(N), warp tile 64x32 = 4x4 m16n8k16.
// A chunks linear (k = ck*32); B chunk k-offset = bTbl[ck]*32.
// sA/sB each hold 3 stages of 8192 bytes (3*128*32 bf16).
__device__ __forceinline__ void gemm_mainloop(
    const __nv_bfloat16* __restrict__ Ap, int strA,
    const __nv_bfloat16* __restrict__ Bp, int strB,
    int nc, const int* __restrict__ bTbl,
    __nv_bfloat16* sA, __nv_bfloat16* sB, float (&c)[4][4][4])
{
    int t = threadIdx.x, lane = t & 31, wid = t >> 5;
    int wm = wid & 1, wn = wid >> 1;
    uint32_t sAu = s2u(sA), sBu = s2u(sB);

    int lr = t >> 2, lg = t & 3;
    uint32_t sw0 = (uint32_t)(lr*64 + ((lg ^ ((lr>>1)&3)) << 4));
    int lr1 = lr + 64;
    uint32_t sw1 = (uint32_t)(lr1*64 + ((lg ^ ((lr1>>1)&3)) << 4));

    int qa = lane >> 3, ra = lane & 7;
    int a_m_local = (qa & 1)*8 + ra;
    int a_gsel = qa >> 1;
    int lb = lane & 15;
    int qb = lb >> 3, rb = lb & 7;

    const __nv_bfloat16* Ap0 = Ap + (size_t)lr *strA + lg*8;
    const __nv_bfloat16* Ap1 = Ap + (size_t)lr1*strA + lg*8;
    const __nv_bfloat16* Bp0 = Bp + (size_t)lr *strB + lg*8;
    const __nv_bfloat16* Bp1 = Bp + (size_t)lr1*strB + lg*8;

    // prologue: stages 0,1 <- chunks 0,1
    {
        cpa16(sAu + sw0, Ap0);
        cpa16(sAu + sw1, Ap1);
        int bo = bTbl[0]*32;
        cpa16(sBu + sw0, Bp0 + bo);
        cpa16(sBu + sw1, Bp1 + bo);
        asm volatile("cp.async.commit_group;");
        cpa16(sAu + 8192 + sw0, Ap0 + 32);
        cpa16(sAu + 8192 + sw1, Ap1 + 32);
        bo = bTbl[1]*32;
        cpa16(sBu + 8192 + sw0, Bp0 + bo);
        cpa16(sBu + 8192 + sw1, Bp1 + bo);
        asm volatile("cp.async.commit_group;");
    }

    for (int ck = 0; ck < nc; ck++) {
        asm volatile("cp.async.wait_group 1;");
        __syncthreads();
        if (ck + 2 < nc) {
            uint32_t st = ((ck + 2) % 3) * 8192;
            int ao = (ck + 2)*32;
            int bo = bTbl[ck + 2]*32;
            cpa16(sAu + st + sw0, Ap0 + ao);
            cpa16(sAu + st + sw1, Ap1 + ao);
            cpa16(sBu + st + sw0, Bp0 + bo);
            cpa16(sBu + st + sw1, Bp1 + bo);
        }
        asm volatile("cp.async.commit_group;");   // empty group in tail keeps counting valid
        uint32_t st8 = (ck % 3) * 8192;
        #pragma unroll
        for (int ks = 0; ks < 2; ks++) {
            uint32_t af[4][4];
            #pragma unroll
            for (int mt = 0; mt < 4; mt++) {
                int m = wm*64 + mt*16 + a_m_local;
                int g = ks*2 + a_gsel;
                uint32_t ad = sAu + st8 + (uint32_t)(m*64 + ((g ^ ((m>>1)&3)) << 4));
                asm volatile("ldmatrix.sync.aligned.m8n8.x4.shared.b16 {%0,%1,%2,%3}, [%4];"
                    : "=r"(af[mt][0]), "=r"(af[mt][1]), "=r"(af[mt][2]), "=r"(af[mt][3]) : "r"(ad));
            }
            uint32_t bf[4][2];
            #pragma unroll
            for (int nt = 0; nt < 4; nt++) {
                int n = wn*32 + nt*8 + rb;
                int g = ks*2 + qb;
                uint32_t bd = sBu + st8 + (uint32_t)(n*64 + ((g ^ ((n>>1)&3)) << 4));
                asm volatile("ldmatrix.sync.aligned.m8n8.x2.shared.b16 {%0,%1}, [%2];"
                    : "=r"(bf[nt][0]), "=r"(bf[nt][1]) : "r"(bd));
            }
            #pragma unroll
            for (int mt = 0; mt < 4; mt++)
                #pragma unroll
                for (int nt = 0; nt < 4; nt++) {
                    asm volatile(
                        "mma.sync.aligned.m16n8k16.row.col.f32.bf16.bf16.f32 "
                        "{%0,%1,%2,%3}, {%4,%5,%6,%7}, {%8,%9}, {%0,%1,%2,%3};"
                        : "+f"(c[mt][nt][0]), "+f"(c[mt][nt][1]), "+f"(c[mt][nt][2]), "+f"(c[mt][nt][3])
                        : "r"(af[mt][0]), "r"(af[mt][1]), "r"(af[mt][2]), "r"(af[mt][3]),
                          "r"(bf[nt][0]), "r"(bf[nt][1]));
                }
        }
    }
}

// ---------------- B split+transpose: g_bt[v][Wh|Wl] from out_w ----------------
__global__ void __launch_bounds__(256) k_bsplit(const float* __restrict__ ow) {
    __shared__ float tile[32][33];
    int v0 = blockIdx.x * 32, k0 = blockIdx.y * 32;
    int tx = threadIdx.x & 31, ty = threadIdx.x >> 5;
    #pragma unroll
    for (int i = 0; i < 4; i++) {
        int k = k0 + ty + 8*i;
        tile[ty + 8*i][tx] = ow[(size_t)k*VV + v0 + tx] + ow[(size_t)(k + 256)*VV + v0 + tx];
    }
    __syncthreads();
    #pragma unroll
    for (int i = 0; i < 4; i++) {
        int v = v0 + ty + 8*i;
        float w = tile[tx][ty + 8*i];
        __nv_bfloat16 h = __float2bfloat16(w);
        __nv_bfloat16 l = __float2bfloat16(w - __bfloat162float(h));
        size_t base = (size_t)v*512 + k0 + tx;
        g_bt[base] = h;          // Wh
        g_bt[base + 256] = l;    // Wl
    }
}

// ---------------- wmean for all layers ----------------
__global__ void k_wmean3(const float* __restrict__ W) {
    int l = blockIdx.x, t = threadIdx.x, lane = t & 31, w = t >> 5;
    for (int r = w; r < DD; r += 8) {
        const float* p = W + (size_t)l*DD*DD + (size_t)r*DD;
        float s = 0.f;
        #pragma unroll
        for (int j = 0; j < 8; j++) s += p[lane + 32*j];
        #pragma unroll
        for (int o = 16; o; o >>= 1) s += __shfl_xor_sync(0xffffffffu, s, o);
        if (lane == 0) g_wmean[l*DD + r] = s * (1.f/DD);
    }
}

// ---------------- embedding + phase space ----------------
__global__ void __launch_bounds__(256) k_phase(const int* __restrict__ x, const float* __restrict__ emb_real,
                        const float* __restrict__ lp, const float* __restrict__ iw,
                        const float* __restrict__ energy, const float* __restrict__ excf) {
    __shared__ float sh[16];
    int row = blockIdx.x, d = threadIdx.x;
    int tok = x[row];
    float re = emb_real[(size_t)tok*DD + d] * 0.1f;
    float fr = 0.f, fi = 0.f;
    const float cav[3] = {1.f, -0.5f, -0.5f};
    const float sav[3] = {0.f, 0.86602540378443865f, -0.86602540378443865f};
    const float PIPHI = 5.083203692315259f;
    #pragma unroll
    for (int i = 0; i < NLY; i++) {
        float pa = tanhf(lp[i*DD + d]) * PIPHI;
        float tr = re * cosf(pa);
        float ti = re * sinf(pa);
        float s1, s2;
        blockSum2(tr, tr*tr, sh, s1, s2);
        float mu = s1 * (1.f/DD);
        float r = (tr - mu) * rsqrtf(fmaxf(s2*(1.f/DD) - mu*mu, 0.f) + 1e-8f);
        blockSum2(ti, ti*ti, sh, s1, s2);
        mu = s1 * (1.f/DD);
        float im = (ti - mu) * rsqrtf(fmaxf(s2*(1.f/DD) - mu*mu, 0.f) + 1e-8f);
        float w = tanhf(iw[i*DD + d]);
        r *= w; im *= w;
        fr += r*cav[i] - im*sav[i];
        fi += r*sav[i] + im*cav[i];
    }
    float amp = sqrtf(fr*fr + fi*fi + 1e-8f);
    float exc = expf(energy[d]) * excf[0];
    if (amp < 0.1f) { fr += exc; fi += exc; }
    float nrm = rsqrtf(fr*fr + fi*fi + 1e-8f);
    g_real[row*DD + d] = clip1(fr * nrm);
    g_imag[row*DD + d] = clip1(fi * nrm);
}

// ---------------- per-layer: LN + operand staging (all coalesced) ----------------
__global__ void __launch_bounds__(256) k_norm(int layer, int first) {
    __shared__ float sh[16];
    int row = blockIdx.x, d = threadIdx.x;
    int idx = row*DD + d;
    float r = g_real[idx];
    float s1, s2;
    blockSum2(r, r*r, sh, s1, s2);
    float mu = s1 * (1.f/DD);
    float nr = (r - mu) * rsqrtf(fmaxf(s2*(1.f/DD) - mu*mu, 0.f) + 1e-5f);
    float ni;
    if (first) {
        float im = g_imag[idx];
        blockSum2(im, im*im, sh, s1, s2);
        mu = s1 * (1.f/DD);
        ni = (im - mu) * rsqrtf(fmaxf(s2*(1.f/DD) - mu*mu, 0.f) + 1e-5f);
    } else {
        ni = nr;   // imag == real after layer 0
    }
    float xx = nr + 1e-8f, yy = ni + 1e-8f;
    float h = rsqrtf(xx*xx + yy*yy);
    float cc = xx*h, ss = yy*h;   // cos/sin(atan2(yy,xx))
    g_c[idx] = cc; g_s[idx] = ss;
    float wm = g_wmean[layer*DD + d];
    g_cw[row*512 + d]       = __float2bfloat16(cc*wm);
    g_cw[row*512 + 256 + d] = __float2bfloat16(ss*wm);
    g_cs[row*512 + d]       = __float2bfloat16(cc);
    g_cs[row*512 + 256 + d] = __float2bfloat16(ss);
    g_nb[row*512 + d]       = __float2bfloat16(nr);
    g_nb[row*512 + 256 + d] = __float2bfloat16(ni);
}

// ---------------- per-layer: transpose g_nb -> g_nT (smem tiled) ----------------
__global__ void __launch_bounds__(256) k_trans() {
    __shared__ __nv_bfloat16 tl[32][33];
    int d0 = blockIdx.x*32, l0 = blockIdx.y*32, b = blockIdx.z;
    int tx = threadIdx.x & 31, ty = threadIdx.x >> 5;
    #pragma unroll
    for (int i = 0; i < 4; i++)
        tl[ty + 8*i][tx] = g_nb[(size_t)(b*LL + l0 + ty + 8*i)*512 + d0 + tx];
    __syncthreads();
    #pragma unroll
    for (int i = 0; i < 4; i++)
        g_nT[(size_t)b*512*LL + (size_t)(d0 + ty + 8*i)*LL + l0 + tx] = tl[tx][ty + 8*i];
}

// ---------------- per-layer: partial column sums for coherence ----------------
__global__ void k_colsum() {
    int b = blockIdx.x, ch = blockIdx.y, d = threadIdx.x;
    float sc = 0.f, ss = 0.f;
    #pragma unroll 4
    for (int m = ch*64; m < ch*64 + 64; m++) {
        int idx = (b*LL + m)*DD + d;
        sc += g_c[idx]; ss += g_s[idx];
    }
    g_scp[(b*6 + ch)*DD + d] = sc;
    g_ssp[(b*6 + ch)*DD + d] = ss;
}

// ---------------- per-layer: scores via HMMA (M=N=384, K=512 per batch) ----------------
__global__ void __launch_bounds__(256) k_scores_mma(const int* __restrict__ x) {
    __shared__ __align__(128) __nv_bfloat16 sA[3*128*32];
    __shared__ __align__(128) __nv_bfloat16 sB[3*128*32];
    int b = blockIdx.z, bm = blockIdx.y*128, bn = blockIdx.x*128;
    float c[4][4][4];
    #pragma unroll
    for (int i = 0; i < 4; i++)
        #pragma unroll
        for (int j = 0; j < 4; j++)
            #pragma unroll
            for (int q = 0; q < 4; q++) c[i][j][q] = 0.f;
    gemm_mainloop(g_cw + (size_t)(b*LL + bm)*512, 512,
                  g_cs + (size_t)(b*LL + bn)*512, 512,
                  16, g_tlin, sA, sB, c);
    int lane = threadIdx.x & 31, wid = threadIdx.x >> 5;
    int wm = wid & 1, wn = wid >> 1;
    int rr0 = lane >> 2, cc0 = (lane & 3)*2;
    #pragma unroll
    for (int mt = 0; mt < 4; mt++)
        #pragma unroll
        for (int nt = 0; nt < 4; nt++) {
            int row = bm + wm*64 + mt*16 + rr0;
            int col = bn + wn*32 + nt*8 + cc0;
            bool p0 = (x[b*LL + col] == 0), p1 = (x[b*LL + col + 1] == 0);
            float2 o;
            o.x = p0 ? (-CUDART_INF_F) : c[mt][nt][0]*0.0625f;
            o.y = p1 ? (-CUDART_INF_F) : c[mt][nt][1]*0.0625f;
            *(float2*)&g_scores[(size_t)(b*LL + row)*LL + col] = o;
            o.x = p0 ? (-CUDART_INF_F) : c[mt][nt][2]*0.0625f;
            o.y = p1 ? (-CUDART_INF_F) : c[mt][nt][3]*0.0625f;
            *(float2*)&g_scores[(size_t)(b*LL + row + 8)*LL + col] = o;
        }
}

// ---------------- per-layer: softmax + clip -> bf16 attn ----------------
__global__ void k_softmax() {
    __shared__ float sh[128];
    int row = blockIdx.x, t = threadIdx.x;
    const float* sc = &g_scores[(size_t)row*LL];
    float v[3], mx = -CUDART_INF_F;
    #pragma unroll
    for (int r = 0; r < 3; r++) { v[r] = sc[t + 128*r]; mx = fmaxf(mx, v[r]); }
    sh[t] = mx; __syncthreads();
    #pragma unroll
    for (int s = 64; s > 0; s >>= 1) { if (t < s) sh[t] = fmaxf(sh[t], sh[t+s]); __syncthreads(); }
    mx = sh[0]; __syncthreads();
    float sum = 0.f;
    #pragma unroll
    for (int r = 0; r < 3; r++) { v[r] = expf(v[r] - mx); sum += v[r]; }
    sh[t] = sum; __syncthreads();
    #pragma unroll
    for (int s = 64; s > 0; s >>= 1) { if (t < s) sh[t] += sh[t+s]; __syncthreads(); }
    float inv = 1.f / sh[0];
    #pragma unroll
    for (int r = 0; r < 3; r++) {
        float p = fminf(fmaxf(v[r]*inv, 1e-6f), 1.f);
        g_attnb[(size_t)row*LL + t + 128*r] = __float2bfloat16(p);
    }
}

// ---------------- per-layer: out = attn @ [nr|ni]^T via HMMA ----------------
__global__ void __launch_bounds__(256) k_out_mma() {
    __shared__ __align__(128) __nv_bfloat16 sA[3*128*32];
    __shared__ __align__(128) __nv_bfloat16 sB[3*128*32];
    int b = blockIdx.z, bm = blockIdx.y*128, bn = blockIdx.x*128;
    float c[4][4][4];
    #pragma unroll
    for (int i = 0; i < 4; i++)
        #pragma unroll
        for (int j = 0; j < 4; j++)
            #pragma unroll
            for (int q = 0; q < 4; q++) c[i][j][q] = 0.f;
    gemm_mainloop(g_attnb + (size_t)(b*LL + bm)*LL, LL,
                  g_nT + (size_t)b*512*LL + (size_t)bn*LL, LL,
                  12, g_tlin, sA, sB, c);
    int lane = threadIdx.x & 31, wid = threadIdx.x >> 5;
    int wm = wid & 1, wn = wid >> 1;
    int rr0 = lane >> 2, cc0 = (lane & 3)*2;
    float* dst = (bn < 256) ? g_outr : g_outi;
    int nb = (bn < 256) ? bn : (bn - 256);
    #pragma unroll
    for (int mt = 0; mt < 4; mt++)
        #pragma unroll
        for (int nt = 0; nt < 4; nt++) {
            int row = bm + wm*64 + mt*16 + rr0;
            int col = nb + wn*32 + nt*8 + cc0;
            float2 o;
            o.x = c[mt][nt][0]; o.y = c[mt][nt][1];
            *(float2*)&dst[(size_t)(b*LL + row)*DD + col] = o;
            o.x = c[mt][nt][2]; o.y = c[mt][nt][3];
            *(float2*)&dst[(size_t)(b*LL + row + 8)*DD + col] = o;
        }
}

// ---------------- per-layer: coherence + phase preservation + residual LN ----------------
__global__ void __launch_bounds__(256) k_update(const float* __restrict__ pp, const float* __restrict__ cohf,
                                                int layer, int last) {
    __shared__ float sh[16];
    int row = blockIdx.x, d = threadIdx.x;
    int b = row / LL;
    float SC = 0.f, SS = 0.f;
    #pragma unroll
    for (int ch = 0; ch < 6; ch++) {
        SC += g_scp[(b*6 + ch)*DD + d];
        SS += g_ssp[(b*6 + ch)*DD + d];
    }
    float part = g_c[row*DD + d]*SC + g_s[row*DD + d]*SS;
    float s1, s2;
    blockSum2(part, part, sh, s1, s2);
    float coh = s1 * (1.f / (float)(LL*DD));
    float cfv = sigm(cohf[layer]) * coh;
    float orv = g_outr[row*DD + d], oiv = g_outi[row*DD + d];
    float phase = atan2f(oiv + 1e-8f, orv + 1e-8f);
    float pres = sigm(pp[layer*DD + d]) * cfv;
    float pr = orv * cosf(phase * pres);
    float val = g_real[row*DD + d] + 0.01f * pr;
    blockSum2(val, val*val, sh, s1, s2);
    float mu = s1 * (1.f/DD);
    float r = clip1((val - mu) * rsqrtf(fmaxf(s2*(1.f/DD) - mu*mu, 0.f) + 1e-8f));
    if (!last) {
        g_real[row*DD + d] = r;
    } else {
        // fused final LN + bf16 hi/lo split
        blockSum2(r, r*r, sh, s1, s2);
        mu = s1 * (1.f/DD);
        float a = (r - mu) * rsqrtf(fmaxf(s2*(1.f/DD) - mu*mu, 0.f) + 1e-5f);
        __nv_bfloat16 h = __float2bfloat16(a);
        __nv_bfloat16 l = __float2bfloat16(a - __bfloat162float(h));
        size_t base = (size_t)row*KP + d;
        g_aexp[base] = h;
        g_aexp[base + 256] = l;
        g_aexp[base + 512] = h;
    }
}

// ---------------- final GEMM via HMMA: C[768,32000] ----------------
// grid (bm=6, bn=250): consecutive CTAs share bn's B tile -> B stays in L2.
__global__ void __launch_bounds__(256) k_gemm_mma(const float* __restrict__ bias, float* __restrict__ out) {
    __shared__ __align__(128) __nv_bfloat16 sA[3*128*32];
    __shared__ __align__(128) __nv_bfloat16 sB[3*128*32];
    int bm = blockIdx.x * 128, bn = blockIdx.y * 128;
    float c[4][4][4];
    #pragma unroll
    for (int i = 0; i < 4; i++)
        #pragma unroll
        for (int j = 0; j < 4; j++)
            #pragma unroll
            for (int q = 0; q < 4; q++) c[i][j][q] = 0.f;
    gemm_mainloop(g_aexp + (size_t)bm*KP, KP,
                  g_bt + (size_t)bn*512, 512,
                  24, g_tsplit, sA, sB, c);
    int lane = threadIdx.x & 31, wid = threadIdx.x >> 5;
    int wm = wid & 1, wn = wid >> 1;
    int rr0 = lane >> 2, cc0 = (lane & 3)*2;
    #pragma unroll
    for (int mt = 0; mt < 4; mt++) {
        #pragma unroll
        for (int nt = 0; nt < 4; nt++) {
            int row = bm + wm*64 + mt*16 + rr0;
            int col = bn + wn*32 + nt*8 + cc0;
            float b0 = bias[col], b1 = bias[col + 1];
            float2 o;
            o.x = fminf(fmaxf((c[mt][nt][0] + b0)*0.1f, -10.f), 10.f);
            o.y = fminf(fmaxf((c[mt][nt][1] + b1)*0.1f, -10.f), 10.f);
            *(float2*)&out[(size_t)row*VV + col] = o;
            o.x = fminf(fmaxf((c[mt][nt][2] + b0)*0.1f, -10.f), 10.f);
            o.y = fminf(fmaxf((c[mt][nt][3] + b1)*0.1f, -10.f), 10.f);
            *(float2*)&out[(size_t)(row + 8)*VV + col] = o;
        }
    }
}

// ---------------- launch ----------------
extern "C" void kernel_launch(void* const* d_in, const int* in_sizes, int n_in,
                              void* d_out, int out_size) {
    const int*   x        = (const int*)  d_in[0];
    const float* emb_real = (const float*)d_in[1];
    // d_in[2] = emb_imag: unused downstream (as in reference)
    const float* lp       = (const float*)d_in[3];
    const float* iw       = (const float*)d_in[4];
    const float* energy   = (const float*)d_in[5];
    const float* excf     = (const float*)d_in[6];
    const float* pp       = (const float*)d_in[7];
    const float* cohf     = (const float*)d_in[8];
    const float* Wattn    = (const float*)d_in[9];
    const float* out_w    = (const float*)d_in[10];
    const float* out_b    = (const float*)d_in[11];
    float* out = (float*)d_out;

    k_bsplit<<<dim3(VV/32, DD/32), 256>>>(out_w);
    k_wmean3<<<NLY, 256>>>(Wattn);
    k_phase<<<BL, 256>>>(x, emb_real, lp, iw, energy, excf);
    for (int i = 0; i < NLY; i++) {
        k_norm<<<BL, 256>>>(i, i == 0 ? 1 : 0);
        k_trans<<<dim3(512/32, LL/32, BB), 256>>>();
        k_colsum<<<dim3(BB, 6), 256>>>();
        k_scores_mma<<<dim3(LL/128, LL/128, BB), 256>>>(x);
        k_softmax<<<BL, 128>>>();
        k_out_mma<<<dim3(512/128, LL/128, BB), 256>>>();
        k_update<<<BL, 256>>>(pp, cohf, i, i == NLY - 1 ? 1 : 0);
    }
    k_gemm_mma<<<dim3(BL/128, VV/128), 256>>>(out_b, out);
}

// round 16
// speedup vs baseline: 1.1027x; 1.1027x over previous
#include <cuda_runtime.h>
#include <cuda_bf16.h>
#include <math_constants.h>
#include <cstdint>

#define BB 2
#define LL 384
#define DD 256
#define VV 32000
#define NLY 3
#define BL (BB*LL)
#define KP 768   // A split-K: [Ah|Al|Ah]; B stored dedup as [Wh|Wl] (512)

// ---------------- scratch (device globals; no allocation) ----------------
__device__ __align__(128) float g_real[BL*DD], g_imag[BL*DD];
__device__ __align__(128) float g_c[BL*DD], g_s[BL*DD];
__device__ __align__(128) float g_outr[BL*DD], g_outi[BL*DD];
__device__ __align__(128) float g_scp[BB*6*DD], g_ssp[BB*6*DD];
__device__ __align__(128) float g_wmean[NLY*DD];
__device__ __align__(128) float g_scores[BB*LL*LL];
__device__ __align__(128) __nv_bfloat16 g_cw[BL*512];            // [row][cw|sw]
__device__ __align__(128) __nv_bfloat16 g_cs[BL*512];            // [row][c|s]
__device__ __align__(128) __nv_bfloat16 g_nb[BL*512];            // [row][nr|ni]
__device__ __align__(128) __nv_bfloat16 g_nT[BB*512*LL];         // [b][d(512)][m]
__device__ __align__(128) __nv_bfloat16 g_attnb[BB*LL*LL];       // [row l][m]
__device__ __align__(128) __nv_bfloat16 g_aexp[BL*KP];
__device__ __align__(128) __nv_bfloat16 g_bt[(size_t)VV*512];    // [v][Wh|Wl] 32.8 MB

// chunk -> B k-offset/32 table for the split-K main GEMM
__device__ const int g_tsplit[24] = {0,1,2,3,4,5,6,7, 0,1,2,3,4,5,6,7, 8,9,10,11,12,13,14,15};

// ---------------- helpers ----------------
__device__ __forceinline__ float clip1(float v) { return fminf(fmaxf(v, -1.f), 1.f); }
__device__ __forceinline__ float sigm(float v) { return 1.f / (1.f + expf(-v)); }

__device__ __forceinline__ void blockSum2(float a, float b, float* sh, float& oa, float& ob) {
    int lane = threadIdx.x & 31, w = threadIdx.x >> 5;
    #pragma unroll
    for (int o = 16; o; o >>= 1) {
        a += __shfl_xor_sync(0xffffffffu, a, o);
        b += __shfl_xor_sync(0xffffffffu, b, o);
    }
    __syncthreads();
    if (lane == 0) { sh[w] = a; sh[8 + w] = b; }
    __syncthreads();
    float sa = 0.f, sb = 0.f;
    #pragma unroll
    for (int i = 0; i < 8; i++) { sa += sh[i]; sb += sh[8 + i]; }
    oa = sa; ob = sb;
}

__device__ __forceinline__ uint32_t s2u(const void* p) {
    uint32_t a;
    asm("{ .reg .u64 t; cvta.to.shared.u64 t, %1; cvt.u32.u64 %0, t; }" : "=r"(a) : "l"(p));
    return a;
}
__device__ __forceinline__ void cpa16(uint32_t s, const void* g) {
    asm volatile("cp.async.cg.shared.global [%0], [%1], 16;" :: "r"(s), "l"(g));
}

// ---------------- 8-warp bf16 HMMA mainloop, cp.async 2-stage (proven R14 shape) ----------------
// CTA 128x128, 8 warps = 2(M) x 4(N), warp tile 64x32 = 4x4 m16n8k16.
// A chunks linear; B chunk k-offset = bTbl[ck]*32. sA/sB: 2 stages x 8192 B.
__device__ __forceinline__ void gemm_mainloop(
    const __nv_bfloat16* __restrict__ Ap, int strA,
    const __nv_bfloat16* __restrict__ Bp, int strB,
    int nc, const int* __restrict__ bTbl,
    __nv_bfloat16* sA, __nv_bfloat16* sB, float (&c)[4][4][4])
{
    int t = threadIdx.x, lane = t & 31, wid = t >> 5;
    int wm = wid & 1, wn = wid >> 1;
    uint32_t sAu = s2u(sA), sBu = s2u(sB);

    int lr = t >> 2, lg = t & 3;
    uint32_t sw0 = (uint32_t)(lr*64 + ((lg ^ ((lr>>1)&3)) << 4));
    int lr1 = lr + 64;
    uint32_t sw1 = (uint32_t)(lr1*64 + ((lg ^ ((lr1>>1)&3)) << 4));

    int qa = lane >> 3, ra = lane & 7;
    int a_m_local = (qa & 1)*8 + ra;
    int a_gsel = qa >> 1;
    int lb = lane & 15;
    int qb = lb >> 3, rb = lb & 7;

    const __nv_bfloat16* Ap0 = Ap + (size_t)lr *strA + lg*8;
    const __nv_bfloat16* Ap1 = Ap + (size_t)lr1*strA + lg*8;
    const __nv_bfloat16* Bp0 = Bp + (size_t)lr *strB + lg*8;
    const __nv_bfloat16* Bp1 = Bp + (size_t)lr1*strB + lg*8;

    // prologue: stage 0 <- chunk 0
    cpa16(sAu + sw0, Ap0);
    cpa16(sAu + sw1, Ap1);
    int bo0 = bTbl[0]*32;
    cpa16(sBu + sw0, Bp0 + bo0);
    cpa16(sBu + sw1, Bp1 + bo0);
    asm volatile("cp.async.commit_group;");

    for (int ck = 0; ck < nc; ck++) {
        asm volatile("cp.async.wait_group 0;");
        __syncthreads();
        if (ck + 1 < nc) {
            uint32_t st = ((ck + 1) & 1) * 8192;
            int ao = (ck + 1)*32;
            int bo = bTbl[ck + 1]*32;
            cpa16(sAu + st + sw0, Ap0 + ao);
            cpa16(sAu + st + sw1, Ap1 + ao);
            cpa16(sBu + st + sw0, Bp0 + bo);
            cpa16(sBu + st + sw1, Bp1 + bo);
            asm volatile("cp.async.commit_group;");
        }
        uint32_t st8 = (ck & 1) * 8192;
        #pragma unroll
        for (int ks = 0; ks < 2; ks++) {
            uint32_t af[4][4];
            #pragma unroll
            for (int mt = 0; mt < 4; mt++) {
                int m = wm*64 + mt*16 + a_m_local;
                int g = ks*2 + a_gsel;
                uint32_t ad = sAu + st8 + (uint32_t)(m*64 + ((g ^ ((m>>1)&3)) << 4));
                asm volatile("ldmatrix.sync.aligned.m8n8.x4.shared.b16 {%0,%1,%2,%3}, [%4];"
                    : "=r"(af[mt][0]), "=r"(af[mt][1]), "=r"(af[mt][2]), "=r"(af[mt][3]) : "r"(ad));
            }
            uint32_t bf[4][2];
            #pragma unroll
            for (int nt = 0; nt < 4; nt++) {
                int n = wn*32 + nt*8 + rb;
                int g = ks*2 + qb;
                uint32_t bd = sBu + st8 + (uint32_t)(n*64 + ((g ^ ((n>>1)&3)) << 4));
                asm volatile("ldmatrix.sync.aligned.m8n8.x2.shared.b16 {%0,%1}, [%2];"
                    : "=r"(bf[nt][0]), "=r"(bf[nt][1]) : "r"(bd));
            }
            #pragma unroll
            for (int mt = 0; mt < 4; mt++)
                #pragma unroll
                for (int nt = 0; nt < 4; nt++) {
                    asm volatile(
                        "mma.sync.aligned.m16n8k16.row.col.f32.bf16.bf16.f32 "
                        "{%0,%1,%2,%3}, {%4,%5,%6,%7}, {%8,%9}, {%0,%1,%2,%3};"
                        : "+f"(c[mt][nt][0]), "+f"(c[mt][nt][1]), "+f"(c[mt][nt][2]), "+f"(c[mt][nt][3])
                        : "r"(af[mt][0]), "r"(af[mt][1]), "r"(af[mt][2]), "r"(af[mt][3]),
                          "r"(bf[nt][0]), "r"(bf[nt][1]));
                }
        }
    }
}

// ---------------- 4-warp 64x64 mainloop (for occupancy-starved attention GEMMs) ----------------
// 128 threads, warps 2(M) x 2(N), warp tile 32x32 = 2x4 m16n8k16. Stages: 2 x 4096 B.
__device__ __forceinline__ void gemm_mainloop64(
    const __nv_bfloat16* __restrict__ Ap, int strA,
    const __nv_bfloat16* __restrict__ Bp, int strB,
    int nc, __nv_bfloat16* sA, __nv_bfloat16* sB, float (&c)[2][4][4])
{
    int t = threadIdx.x, lane = t & 31, wid = t >> 5;
    int wm = wid & 1, wn = wid >> 1;
    uint32_t sAu = s2u(sA), sBu = s2u(sB);

    int lr = t >> 2, lg = t & 3;        // rows 0..31, 16B group 0..3
    uint32_t sw0 = (uint32_t)(lr*64 + ((lg ^ ((lr>>1)&3)) << 4));
    int lr1 = lr + 32;
    uint32_t sw1 = (uint32_t)(lr1*64 + ((lg ^ ((lr1>>1)&3)) << 4));

    int qa = lane >> 3, ra = lane & 7;
    int a_m_local = (qa & 1)*8 + ra;
    int a_gsel = qa >> 1;
    int lb = lane & 15;
    int qb = lb >> 3, rb = lb & 7;

    const __nv_bfloat16* Ap0 = Ap + (size_t)lr *strA + lg*8;
    const __nv_bfloat16* Ap1 = Ap + (size_t)lr1*strA + lg*8;
    const __nv_bfloat16* Bp0 = Bp + (size_t)lr *strB + lg*8;
    const __nv_bfloat16* Bp1 = Bp + (size_t)lr1*strB + lg*8;

    cpa16(sAu + sw0, Ap0);
    cpa16(sAu + sw1, Ap1);
    cpa16(sBu + sw0, Bp0);
    cpa16(sBu + sw1, Bp1);
    asm volatile("cp.async.commit_group;");

    for (int ck = 0; ck < nc; ck++) {
        asm volatile("cp.async.wait_group 0;");
        __syncthreads();
        if (ck + 1 < nc) {
            uint32_t st = ((ck + 1) & 1) * 4096;
            int o = (ck + 1)*32;
            cpa16(sAu + st + sw0, Ap0 + o);
            cpa16(sAu + st + sw1, Ap1 + o);
            cpa16(sBu + st + sw0, Bp0 + o);
            cpa16(sBu + st + sw1, Bp1 + o);
            asm volatile("cp.async.commit_group;");
        }
        uint32_t st8 = (ck & 1) * 4096;
        #pragma unroll
        for (int ks = 0; ks < 2; ks++) {
            uint32_t af[2][4];
            #pragma unroll
            for (int mt = 0; mt < 2; mt++) {
                int m = wm*32 + mt*16 + a_m_local;
                int g = ks*2 + a_gsel;
                uint32_t ad = sAu + st8 + (uint32_t)(m*64 + ((g ^ ((m>>1)&3)) << 4));
                asm volatile("ldmatrix.sync.aligned.m8n8.x4.shared.b16 {%0,%1,%2,%3}, [%4];"
                    : "=r"(af[mt][0]), "=r"(af[mt][1]), "=r"(af[mt][2]), "=r"(af[mt][3]) : "r"(ad));
            }
            uint32_t bf[4][2];
            #pragma unroll
            for (int nt = 0; nt < 4; nt++) {
                int n = wn*32 + nt*8 + rb;
                int g = ks*2 + qb;
                uint32_t bd = sBu + st8 + (uint32_t)(n*64 + ((g ^ ((n>>1)&3)) << 4));
                asm volatile("ldmatrix.sync.aligned.m8n8.x2.shared.b16 {%0,%1}, [%2];"
                    : "=r"(bf[nt][0]), "=r"(bf[nt][1]) : "r"(bd));
            }
            #pragma unroll
            for (int mt = 0; mt < 2; mt++)
                #pragma unroll
                for (int nt = 0; nt < 4; nt++) {
                    asm volatile(
                        "mma.sync.aligned.m16n8k16.row.col.f32.bf16.bf16.f32 "
                        "{%0,%1,%2,%3}, {%4,%5,%6,%7}, {%8,%9}, {%0,%1,%2,%3};"
                        : "+f"(c[mt][nt][0]), "+f"(c[mt][nt][1]), "+f"(c[mt][nt][2]), "+f"(c[mt][nt][3])
                        : "r"(af[mt][0]), "r"(af[mt][1]), "r"(af[mt][2]), "r"(af[mt][3]),
                          "r"(bf[nt][0]), "r"(bf[nt][1]));
                }
        }
    }
}

// ---------------- B split+transpose: g_bt[v][Wh|Wl] from out_w ----------------
__global__ void __launch_bounds__(256) k_bsplit(const float* __restrict__ ow) {
    __shared__ float tile[32][33];
    int v0 = blockIdx.x * 32, k0 = blockIdx.y * 32;
    int tx = threadIdx.x & 31, ty = threadIdx.x >> 5;
    #pragma unroll
    for (int i = 0; i < 4; i++) {
        int k = k0 + ty + 8*i;
        tile[ty + 8*i][tx] = ow[(size_t)k*VV + v0 + tx] + ow[(size_t)(k + 256)*VV + v0 + tx];
    }
    __syncthreads();
    #pragma unroll
    for (int i = 0; i < 4; i++) {
        int v = v0 + ty + 8*i;
        float w = tile[tx][ty + 8*i];
        __nv_bfloat16 h = __float2bfloat16(w);
        __nv_bfloat16 l = __float2bfloat16(w - __bfloat162float(h));
        size_t base = (size_t)v*512 + k0 + tx;
        g_bt[base] = h;
        g_bt[base + 256] = l;
    }
}

// ---------------- wmean for all layers ----------------
__global__ void k_wmean3(const float* __restrict__ W) {
    int l = blockIdx.x, t = threadIdx.x, lane = t & 31, w = t >> 5;
    for (int r = w; r < DD; r += 8) {
        const float* p = W + (size_t)l*DD*DD + (size_t)r*DD;
        float s = 0.f;
        #pragma unroll
        for (int j = 0; j < 8; j++) s += p[lane + 32*j];
        #pragma unroll
        for (int o = 16; o; o >>= 1) s += __shfl_xor_sync(0xffffffffu, s, o);
        if (lane == 0) g_wmean[l*DD + r] = s * (1.f/DD);
    }
}

// ---------------- embedding + phase space ----------------
__global__ void __launch_bounds__(256) k_phase(const int* __restrict__ x, const float* __restrict__ emb_real,
                        const float* __restrict__ lp, const float* __restrict__ iw,
                        const float* __restrict__ energy, const float* __restrict__ excf) {
    __shared__ float sh[16];
    int row = blockIdx.x, d = threadIdx.x;
    int tok = x[row];
    float re = emb_real[(size_t)tok*DD + d] * 0.1f;
    float fr = 0.f, fi = 0.f;
    const float cav[3] = {1.f, -0.5f, -0.5f};
    const float sav[3] = {0.f, 0.86602540378443865f, -0.86602540378443865f};
    const float PIPHI = 5.083203692315259f;
    #pragma unroll
    for (int i = 0; i < NLY; i++) {
        float pa = tanhf(lp[i*DD + d]) * PIPHI;
        float tr = re * cosf(pa);
        float ti = re * sinf(pa);
        float s1, s2;
        blockSum2(tr, tr*tr, sh, s1, s2);
        float mu = s1 * (1.f/DD);
        float r = (tr - mu) * rsqrtf(fmaxf(s2*(1.f/DD) - mu*mu, 0.f) + 1e-8f);
        blockSum2(ti, ti*ti, sh, s1, s2);
        mu = s1 * (1.f/DD);
        float im = (ti - mu) * rsqrtf(fmaxf(s2*(1.f/DD) - mu*mu, 0.f) + 1e-8f);
        float w = tanhf(iw[i*DD + d]);
        r *= w; im *= w;
        fr += r*cav[i] - im*sav[i];
        fi += r*sav[i] + im*cav[i];
    }
    float amp = sqrtf(fr*fr + fi*fi + 1e-8f);
    float exc = expf(energy[d]) * excf[0];
    if (amp < 0.1f) { fr += exc; fi += exc; }
    float nrm = rsqrtf(fr*fr + fi*fi + 1e-8f);
    g_real[row*DD + d] = clip1(fr * nrm);
    g_imag[row*DD + d] = clip1(fi * nrm);
}

// ---------------- layer 0 only: LN + operand staging ----------------
__global__ void __launch_bounds__(256) k_norm0() {
    __shared__ float sh[16];
    int row = blockIdx.x, d = threadIdx.x;
    int idx = row*DD + d;
    float r = g_real[idx];
    float s1, s2;
    blockSum2(r, r*r, sh, s1, s2);
    float mu = s1 * (1.f/DD);
    float nr = (r - mu) * rsqrtf(fmaxf(s2*(1.f/DD) - mu*mu, 0.f) + 1e-5f);
    float im = g_imag[idx];
    blockSum2(im, im*im, sh, s1, s2);
    mu = s1 * (1.f/DD);
    float ni = (im - mu) * rsqrtf(fmaxf(s2*(1.f/DD) - mu*mu, 0.f) + 1e-5f);
    float xx = nr + 1e-8f, yy = ni + 1e-8f;
    float h = rsqrtf(xx*xx + yy*yy);
    float cc = xx*h, ss = yy*h;
    g_c[idx] = cc; g_s[idx] = ss;
    float wm = g_wmean[d];
    g_cw[row*512 + d]       = __float2bfloat16(cc*wm);
    g_cw[row*512 + 256 + d] = __float2bfloat16(ss*wm);
    g_cs[row*512 + d]       = __float2bfloat16(cc);
    g_cs[row*512 + 256 + d] = __float2bfloat16(ss);
    g_nb[row*512 + d]       = __float2bfloat16(nr);
    g_nb[row*512 + 256 + d] = __float2bfloat16(ni);
}

// ---------------- per-layer: transpose g_nb -> g_nT (smem tiled) ----------------
__global__ void __launch_bounds__(256) k_trans() {
    __shared__ __nv_bfloat16 tl[32][33];
    int d0 = blockIdx.x*32, l0 = blockIdx.y*32, b = blockIdx.z;
    int tx = threadIdx.x & 31, ty = threadIdx.x >> 5;
    #pragma unroll
    for (int i = 0; i < 4; i++)
        tl[ty + 8*i][tx] = g_nb[(size_t)(b*LL + l0 + ty + 8*i)*512 + d0 + tx];
    __syncthreads();
    #pragma unroll
    for (int i = 0; i < 4; i++)
        g_nT[(size_t)b*512*LL + (size_t)(d0 + ty + 8*i)*LL + l0 + tx] = tl[tx][ty + 8*i];
}

// ---------------- per-layer: partial column sums for coherence ----------------
__global__ void k_colsum() {
    int b = blockIdx.x, ch = blockIdx.y, d = threadIdx.x;
    float sc = 0.f, ss = 0.f;
    #pragma unroll 4
    for (int m = ch*64; m < ch*64 + 64; m++) {
        int idx = (b*LL + m)*DD + d;
        sc += g_c[idx]; ss += g_s[idx];
    }
    g_scp[(b*6 + ch)*DD + d] = sc;
    g_ssp[(b*6 + ch)*DD + d] = ss;
}

// ---------------- per-layer: scores via 64x64 HMMA ----------------
__global__ void __launch_bounds__(128) k_scores_mma(const int* __restrict__ x) {
    __shared__ __align__(128) __nv_bfloat16 sA[2*64*32];
    __shared__ __align__(128) __nv_bfloat16 sB[2*64*32];
    int b = blockIdx.z, bm = blockIdx.y*64, bn = blockIdx.x*64;
    float c[2][4][4];
    #pragma unroll
    for (int i = 0; i < 2; i++)
        #pragma unroll
        for (int j = 0; j < 4; j++)
            #pragma unroll
            for (int q = 0; q < 4; q++) c[i][j][q] = 0.f;
    gemm_mainloop64(g_cw + (size_t)(b*LL + bm)*512, 512,
                    g_cs + (size_t)(b*LL + bn)*512, 512,
                    16, sA, sB, c);
    int lane = threadIdx.x & 31, wid = threadIdx.x >> 5;
    int wm = wid & 1, wn = wid >> 1;
    int rr0 = lane >> 2, cc0 = (lane & 3)*2;
    #pragma unroll
    for (int mt = 0; mt < 2; mt++)
        #pragma unroll
        for (int nt = 0; nt < 4; nt++) {
            int row = bm + wm*32 + mt*16 + rr0;
            int col = bn + wn*32 + nt*8 + cc0;
            bool p0 = (x[b*LL + col] == 0), p1 = (x[b*LL + col + 1] == 0);
            float2 o;
            o.x = p0 ? (-CUDART_INF_F) : c[mt][nt][0]*0.0625f;
            o.y = p1 ? (-CUDART_INF_F) : c[mt][nt][1]*0.0625f;
            *(float2*)&g_scores[(size_t)(b*LL + row)*LL + col] = o;
            o.x = p0 ? (-CUDART_INF_F) : c[mt][nt][2]*0.0625f;
            o.y = p1 ? (-CUDART_INF_F) : c[mt][nt][3]*0.0625f;
            *(float2*)&g_scores[(size_t)(b*LL + row + 8)*LL + col] = o;
        }
}

// ---------------- per-layer: softmax + clip -> bf16 attn ----------------
__global__ void k_softmax() {
    __shared__ float sh[128];
    int row = blockIdx.x, t = threadIdx.x;
    const float* sc = &g_scores[(size_t)row*LL];
    float v[3], mx = -CUDART_INF_F;
    #pragma unroll
    for (int r = 0; r < 3; r++) { v[r] = sc[t + 128*r]; mx = fmaxf(mx, v[r]); }
    sh[t] = mx; __syncthreads();
    #pragma unroll
    for (int s = 64; s > 0; s >>= 1) { if (t < s) sh[t] = fmaxf(sh[t], sh[t+s]); __syncthreads(); }
    mx = sh[0]; __syncthreads();
    float sum = 0.f;
    #pragma unroll
    for (int r = 0; r < 3; r++) { v[r] = expf(v[r] - mx); sum += v[r]; }
    sh[t] = sum; __syncthreads();
    #pragma unroll
    for (int s = 64; s > 0; s >>= 1) { if (t < s) sh[t] += sh[t+s]; __syncthreads(); }
    float inv = 1.f / sh[0];
    #pragma unroll
    for (int r = 0; r < 3; r++) {
        float p = fminf(fmaxf(v[r]*inv, 1e-6f), 1.f);
        g_attnb[(size_t)row*LL + t + 128*r] = __float2bfloat16(p);
    }
}

// ---------------- per-layer: out = attn @ [nr|ni]^T via 64x64 HMMA ----------------
__global__ void __launch_bounds__(128) k_out_mma() {
    __shared__ __align__(128) __nv_bfloat16 sA[2*64*32];
    __shared__ __align__(128) __nv_bfloat16 sB[2*64*32];
    int b = blockIdx.z, bm = blockIdx.y*64, bn = blockIdx.x*64;
    float c[2][4][4];
    #pragma unroll
    for (int i = 0; i < 2; i++)
        #pragma unroll
        for (int j = 0; j < 4; j++)
            #pragma unroll
            for (int q = 0; q < 4; q++) c[i][j][q] = 0.f;
    gemm_mainloop64(g_attnb + (size_t)(b*LL + bm)*LL, LL,
                    g_nT + (size_t)b*512*LL + (size_t)bn*LL, LL,
                    12, sA, sB, c);
    int lane = threadIdx.x & 31, wid = threadIdx.x >> 5;
    int wm = wid & 1, wn = wid >> 1;
    int rr0 = lane >> 2, cc0 = (lane & 3)*2;
    float* dst = (bn < 256) ? g_outr : g_outi;
    int nb = (bn < 256) ? bn : (bn - 256);
    #pragma unroll
    for (int mt = 0; mt < 2; mt++)
        #pragma unroll
        for (int nt = 0; nt < 4; nt++) {
            int row = bm + wm*32 + mt*16 + rr0;
            int col = nb + wn*32 + nt*8 + cc0;
            float2 o;
            o.x = c[mt][nt][0]; o.y = c[mt][nt][1];
            *(float2*)&dst[(size_t)(b*LL + row)*DD + col] = o;
            o.x = c[mt][nt][2]; o.y = c[mt][nt][3];
            *(float2*)&dst[(size_t)(b*LL + row + 8)*DD + col] = o;
        }
}

// ---------------- per-layer: coherence + residual LN, FUSED with next-layer norm staging ----
// last!=0: final LN + bf16 hi/lo split instead of staging.
__global__ void __launch_bounds__(256) k_update(const float* __restrict__ pp, const float* __restrict__ cohf,
                                                int layer, int last) {
    __shared__ float sh[16];
    int row = blockIdx.x, d = threadIdx.x;
    int b = row / LL;
    float SC = 0.f, SS = 0.f;
    #pragma unroll
    for (int ch = 0; ch < 6; ch++) {
        SC += g_scp[(b*6 + ch)*DD + d];
        SS += g_ssp[(b*6 + ch)*DD + d];
    }
    float part = g_c[row*DD + d]*SC + g_s[row*DD + d]*SS;
    float s1, s2;
    blockSum2(part, part, sh, s1, s2);
    float coh = s1 * (1.f / (float)(LL*DD));
    float cfv = sigm(cohf[layer]) * coh;
    float orv = g_outr[row*DD + d], oiv = g_outi[row*DD + d];
    float phase = atan2f(oiv + 1e-8f, orv + 1e-8f);
    float pres = sigm(pp[layer*DD + d]) * cfv;
    float pr = orv * cosf(phase * pres);
    float val = g_real[row*DD + d] + 0.01f * pr;
    blockSum2(val, val*val, sh, s1, s2);
    float mu = s1 * (1.f/DD);
    float r = clip1((val - mu) * rsqrtf(fmaxf(s2*(1.f/DD) - mu*mu, 0.f) + 1e-8f));
    if (!last) {
        g_real[row*DD + d] = r;   // residual base for layer+1's update
        // fused next-layer norm staging (first=0 -> ni = nr)
        blockSum2(r, r*r, sh, s1, s2);
        mu = s1 * (1.f/DD);
        float nr = (r - mu) * rsqrtf(fmaxf(s2*(1.f/DD) - mu*mu, 0.f) + 1e-5f);
        float ni = nr;
        float xx = nr + 1e-8f, yy = ni + 1e-8f;
        float h = rsqrtf(xx*xx + yy*yy);
        float cc = xx*h, ss = yy*h;
        int idx = row*DD + d;
        g_c[idx] = cc; g_s[idx] = ss;
        float wm = g_wmean[(layer + 1)*DD + d];
        g_cw[row*512 + d]       = __float2bfloat16(cc*wm);
        g_cw[row*512 + 256 + d] = __float2bfloat16(ss*wm);
        g_cs[row*512 + d]       = __float2bfloat16(cc);
        g_cs[row*512 + 256 + d] = __float2bfloat16(ss);
        g_nb[row*512 + d]       = __float2bfloat16(nr);
        g_nb[row*512 + 256 + d] = __float2bfloat16(ni);
    } else {
        // fused final LN + bf16 hi/lo split
        blockSum2(r, r*r, sh, s1, s2);
        mu = s1 * (1.f/DD);
        float a = (r - mu) * rsqrtf(fmaxf(s2*(1.f/DD) - mu*mu, 0.f) + 1e-5f);
        __nv_bfloat16 h = __float2bfloat16(a);
        __nv_bfloat16 l = __float2bfloat16(a - __bfloat162float(h));
        size_t base = (size_t)row*KP + d;
        g_aexp[base] = h;
        g_aexp[base + 256] = l;
        g_aexp[base + 512] = h;
    }
}

// ---------------- final GEMM via HMMA: C[768,32000] ----------------
__global__ void __launch_bounds__(256) k_gemm_mma(const float* __restrict__ bias, float* __restrict__ out) {
    __shared__ __align__(128) __nv_bfloat16 sA[2*128*32];
    __shared__ __align__(128) __nv_bfloat16 sB[2*128*32];
    int bm = blockIdx.x * 128, bn = blockIdx.y * 128;
    float c[4][4][4];
    #pragma unroll
    for (int i = 0; i < 4; i++)
        #pragma unroll
        for (int j = 0; j < 4; j++)
            #pragma unroll
            for (int q = 0; q < 4; q++) c[i][j][q] = 0.f;
    gemm_mainloop(g_aexp + (size_t)bm*KP, KP,
                  g_bt + (size_t)bn*512, 512,
                  24, g_tsplit, sA, sB, c);
    int lane = threadIdx.x & 31, wid = threadIdx.x >> 5;
    int wm = wid & 1, wn = wid >> 1;
    int rr0 = lane >> 2, cc0 = (lane & 3)*2;
    #pragma unroll
    for (int mt = 0; mt < 4; mt++) {
        #pragma unroll
        for (int nt = 0; nt < 4; nt++) {
            int row = bm + wm*64 + mt*16 + rr0;
            int col = bn + wn*32 + nt*8 + cc0;
            float b0 = bias[col], b1 = bias[col + 1];
            float2 o;
            o.x = fminf(fmaxf((c[mt][nt][0] + b0)*0.1f, -10.f), 10.f);
            o.y = fminf(fmaxf((c[mt][nt][1] + b1)*0.1f, -10.f), 10.f);
            *(float2*)&out[(size_t)row*VV + col] = o;
            o.x = fminf(fmaxf((c[mt][nt][2] + b0)*0.1f, -10.f), 10.f);
            o.y = fminf(fmaxf((c[mt][nt][3] + b1)*0.1f, -10.f), 10.f);
            *(float2*)&out[(size_t)(row + 8)*VV + col] = o;
        }
    }
}

// ---------------- launch ----------------
extern "C" void kernel_launch(void* const* d_in, const int* in_sizes, int n_in,
                              void* d_out, int out_size) {
    const int*   x        = (const int*)  d_in[0];
    const float* emb_real = (const float*)d_in[1];
    // d_in[2] = emb_imag: unused downstream (as in reference)
    const float* lp       = (const float*)d_in[3];
    const float* iw       = (const float*)d_in[4];
    const float* energy   = (const float*)d_in[5];
    const float* excf     = (const float*)d_in[6];
    const float* pp       = (const float*)d_in[7];
    const float* cohf     = (const float*)d_in[8];
    const float* Wattn    = (const float*)d_in[9];
    const float* out_w    = (const float*)d_in[10];
    const float* out_b    = (const float*)d_in[11];
    float* out = (float*)d_out;

    k_bsplit<<<dim3(VV/32, DD/32), 256>>>(out_w);
    k_wmean3<<<NLY, 256>>>(Wattn);
    k_phase<<<BL, 256>>>(x, emb_real, lp, iw, energy, excf);
    k_norm0<<<BL, 256>>>();
    for (int i = 0; i < NLY; i++) {
        k_trans<<<dim3(512/32, LL/32, BB), 256>>>();
        k_colsum<<<dim3(BB, 6), 256>>>();
        k_scores_mma<<<dim3(LL/64, LL/64, BB), 128>>>(x);
        k_softmax<<<BL, 128>>>();
        k_out_mma<<<dim3(512/64, LL/64, BB), 128>>>();
        k_update<<<BL, 256>>>(pp, cohf, i, i == NLY - 1 ? 1 : 0);
    }
    k_gemm_mma<<<dim3(BL/128, VV/128), 256>>>(out_b, out);
}

// round 17
// speedup vs baseline: 1.2660x; 1.1481x over previous
#include <cuda_runtime.h>
#include <cuda_fp16.h>
#include <math_constants.h>
#include <cstdint>

#define BB 2
#define LL 384
#define DD 256
#define VV 32000
#define NLY 3
#define BL (BB*LL)
#define KPA 512  // A: [Ah|Al] fp16; B: [Wh] only (both chunks hit Wh)

// ---------------- scratch (device globals; no allocation) ----------------
__device__ __align__(128) float g_real[BL*DD], g_imag[BL*DD];
__device__ __align__(128) float g_c[BL*DD], g_s[BL*DD];
__device__ __align__(128) float g_outr[BL*DD], g_outi[BL*DD];
__device__ __align__(128) float g_scp[BB*6*DD], g_ssp[BB*6*DD];
__device__ __align__(128) float g_wmean[NLY*DD];
__device__ __align__(128) float g_scores[BB*LL*LL];
__device__ __align__(128) __half g_cw[BL*512];            // [row][cw|sw]
__device__ __align__(128) __half g_cs[BL*512];            // [row][c|s]
__device__ __align__(128) __half g_nb[BL*512];            // [row][nr|ni]
__device__ __align__(128) __half g_nT[BB*512*LL];         // [b][d(512)][m]
__device__ __align__(128) __half g_attnb[BB*LL*LL];       // [row l][m]
__device__ __align__(128) __half g_aexp[BL*KPA];          // [row][Ah|Al]
__device__ __align__(128) __half g_bt[(size_t)VV*DD];     // [v][Wh] 16.4 MB

// chunk -> B k-offset/32 table for the split-K main GEMM (A linear, B wraps)
__device__ const int g_tsplit[16] = {0,1,2,3,4,5,6,7, 0,1,2,3,4,5,6,7};

// ---------------- helpers ----------------
__device__ __forceinline__ float clip1(float v) { return fminf(fmaxf(v, -1.f), 1.f); }
__device__ __forceinline__ float sigm(float v) { return 1.f / (1.f + expf(-v)); }

__device__ __forceinline__ void blockSum2(float a, float b, float* sh, float& oa, float& ob) {
    int lane = threadIdx.x & 31, w = threadIdx.x >> 5;
    #pragma unroll
    for (int o = 16; o; o >>= 1) {
        a += __shfl_xor_sync(0xffffffffu, a, o);
        b += __shfl_xor_sync(0xffffffffu, b, o);
    }
    __syncthreads();
    if (lane == 0) { sh[w] = a; sh[8 + w] = b; }
    __syncthreads();
    float sa = 0.f, sb = 0.f;
    #pragma unroll
    for (int i = 0; i < 8; i++) { sa += sh[i]; sb += sh[8 + i]; }
    oa = sa; ob = sb;
}

__device__ __forceinline__ uint32_t s2u(const void* p) {
    uint32_t a;
    asm("{ .reg .u64 t; cvta.to.shared.u64 t, %1; cvt.u32.u64 %0, t; }" : "=r"(a) : "l"(p));
    return a;
}
__device__ __forceinline__ void cpa16(uint32_t s, const void* g) {
    asm volatile("cp.async.cg.shared.global [%0], [%1], 16;" :: "r"(s), "l"(g));
}

// ---------------- 8-warp fp16 HMMA mainloop, cp.async 2-stage ----------------
// CTA 128x128, 8 warps = 2(M) x 4(N), warp tile 64x32 = 4x4 m16n8k16.
// A chunks linear; B chunk k-offset = bTbl[ck]*32. sA/sB: 2 stages x 8192 B.
__device__ __forceinline__ void gemm_mainloop(
    const __half* __restrict__ Ap, int strA,
    const __half* __restrict__ Bp, int strB,
    int nc, const int* __restrict__ bTbl,
    __half* sA, __half* sB, float (&c)[4][4][4])
{
    int t = threadIdx.x, lane = t & 31, wid = t >> 5;
    int wm = wid & 1, wn = wid >> 1;
    uint32_t sAu = s2u(sA), sBu = s2u(sB);

    int lr = t >> 2, lg = t & 3;
    uint32_t sw0 = (uint32_t)(lr*64 + ((lg ^ ((lr>>1)&3)) << 4));
    int lr1 = lr + 64;
    uint32_t sw1 = (uint32_t)(lr1*64 + ((lg ^ ((lr1>>1)&3)) << 4));

    int qa = lane >> 3, ra = lane & 7;
    int a_m_local = (qa & 1)*8 + ra;
    int a_gsel = qa >> 1;
    int lb = lane & 15;
    int qb = lb >> 3, rb = lb & 7;

    const __half* Ap0 = Ap + (size_t)lr *strA + lg*8;
    const __half* Ap1 = Ap + (size_t)lr1*strA + lg*8;
    const __half* Bp0 = Bp + (size_t)lr *strB + lg*8;
    const __half* Bp1 = Bp + (size_t)lr1*strB + lg*8;

    cpa16(sAu + sw0, Ap0);
    cpa16(sAu + sw1, Ap1);
    int bo0 = bTbl[0]*32;
    cpa16(sBu + sw0, Bp0 + bo0);
    cpa16(sBu + sw1, Bp1 + bo0);
    asm volatile("cp.async.commit_group;");

    for (int ck = 0; ck < nc; ck++) {
        asm volatile("cp.async.wait_group 0;");
        __syncthreads();
        if (ck + 1 < nc) {
            uint32_t st = ((ck + 1) & 1) * 8192;
            int ao = (ck + 1)*32;
            int bo = bTbl[ck + 1]*32;
            cpa16(sAu + st + sw0, Ap0 + ao);
            cpa16(sAu + st + sw1, Ap1 + ao);
            cpa16(sBu + st + sw0, Bp0 + bo);
            cpa16(sBu + st + sw1, Bp1 + bo);
            asm volatile("cp.async.commit_group;");
        }
        uint32_t st8 = (ck & 1) * 8192;
        #pragma unroll
        for (int ks = 0; ks < 2; ks++) {
            uint32_t af[4][4];
            #pragma unroll
            for (int mt = 0; mt < 4; mt++) {
                int m = wm*64 + mt*16 + a_m_local;
                int g = ks*2 + a_gsel;
                uint32_t ad = sAu + st8 + (uint32_t)(m*64 + ((g ^ ((m>>1)&3)) << 4));
                asm volatile("ldmatrix.sync.aligned.m8n8.x4.shared.b16 {%0,%1,%2,%3}, [%4];"
                    : "=r"(af[mt][0]), "=r"(af[mt][1]), "=r"(af[mt][2]), "=r"(af[mt][3]) : "r"(ad));
            }
            uint32_t bf[4][2];
            #pragma unroll
            for (int nt = 0; nt < 4; nt++) {
                int n = wn*32 + nt*8 + rb;
                int g = ks*2 + qb;
                uint32_t bd = sBu + st8 + (uint32_t)(n*64 + ((g ^ ((n>>1)&3)) << 4));
                asm volatile("ldmatrix.sync.aligned.m8n8.x2.shared.b16 {%0,%1}, [%2];"
                    : "=r"(bf[nt][0]), "=r"(bf[nt][1]) : "r"(bd));
            }
            #pragma unroll
            for (int mt = 0; mt < 4; mt++)
                #pragma unroll
                for (int nt = 0; nt < 4; nt++) {
                    asm volatile(
                        "mma.sync.aligned.m16n8k16.row.col.f32.f16.f16.f32 "
                        "{%0,%1,%2,%3}, {%4,%5,%6,%7}, {%8,%9}, {%0,%1,%2,%3};"
                        : "+f"(c[mt][nt][0]), "+f"(c[mt][nt][1]), "+f"(c[mt][nt][2]), "+f"(c[mt][nt][3])
                        : "r"(af[mt][0]), "r"(af[mt][1]), "r"(af[mt][2]), "r"(af[mt][3]),
                          "r"(bf[nt][0]), "r"(bf[nt][1]));
                }
        }
    }
}

// ---------------- 4-warp 64x64 mainloop (attention GEMMs) ----------------
__device__ __forceinline__ void gemm_mainloop64(
    const __half* __restrict__ Ap, int strA,
    const __half* __restrict__ Bp, int strB,
    int nc, __half* sA, __half* sB, float (&c)[2][4][4])
{
    int t = threadIdx.x, lane = t & 31, wid = t >> 5;
    int wm = wid & 1, wn = wid >> 1;
    uint32_t sAu = s2u(sA), sBu = s2u(sB);

    int lr = t >> 2, lg = t & 3;
    uint32_t sw0 = (uint32_t)(lr*64 + ((lg ^ ((lr>>1)&3)) << 4));
    int lr1 = lr + 32;
    uint32_t sw1 = (uint32_t)(lr1*64 + ((lg ^ ((lr1>>1)&3)) << 4));

    int qa = lane >> 3, ra = lane & 7;
    int a_m_local = (qa & 1)*8 + ra;
    int a_gsel = qa >> 1;
    int lb = lane & 15;
    int qb = lb >> 3, rb = lb & 7;

    const __half* Ap0 = Ap + (size_t)lr *strA + lg*8;
    const __half* Ap1 = Ap + (size_t)lr1*strA + lg*8;
    const __half* Bp0 = Bp + (size_t)lr *strB + lg*8;
    const __half* Bp1 = Bp + (size_t)lr1*strB + lg*8;

    cpa16(sAu + sw0, Ap0);
    cpa16(sAu + sw1, Ap1);
    cpa16(sBu + sw0, Bp0);
    cpa16(sBu + sw1, Bp1);
    asm volatile("cp.async.commit_group;");

    for (int ck = 0; ck < nc; ck++) {
        asm volatile("cp.async.wait_group 0;");
        __syncthreads();
        if (ck + 1 < nc) {
            uint32_t st = ((ck + 1) & 1) * 4096;
            int o = (ck + 1)*32;
            cpa16(sAu + st + sw0, Ap0 + o);
            cpa16(sAu + st + sw1, Ap1 + o);
            cpa16(sBu + st + sw0, Bp0 + o);
            cpa16(sBu + st + sw1, Bp1 + o);
            asm volatile("cp.async.commit_group;");
        }
        uint32_t st8 = (ck & 1) * 4096;
        #pragma unroll
        for (int ks = 0; ks < 2; ks++) {
            uint32_t af[2][4];
            #pragma unroll
            for (int mt = 0; mt < 2; mt++) {
                int m = wm*32 + mt*16 + a_m_local;
                int g = ks*2 + a_gsel;
                uint32_t ad = sAu + st8 + (uint32_t)(m*64 + ((g ^ ((m>>1)&3)) << 4));
                asm volatile("ldmatrix.sync.aligned.m8n8.x4.shared.b16 {%0,%1,%2,%3}, [%4];"
                    : "=r"(af[mt][0]), "=r"(af[mt][1]), "=r"(af[mt][2]), "=r"(af[mt][3]) : "r"(ad));
            }
            uint32_t bf[4][2];
            #pragma unroll
            for (int nt = 0; nt < 4; nt++) {
                int n = wn*32 + nt*8 + rb;
                int g = ks*2 + qb;
                uint32_t bd = sBu + st8 + (uint32_t)(n*64 + ((g ^ ((n>>1)&3)) << 4));
                asm volatile("ldmatrix.sync.aligned.m8n8.x2.shared.b16 {%0,%1}, [%2];"
                    : "=r"(bf[nt][0]), "=r"(bf[nt][1]) : "r"(bd));
            }
            #pragma unroll
            for (int mt = 0; mt < 2; mt++)
                #pragma unroll
                for (int nt = 0; nt < 4; nt++) {
                    asm volatile(
                        "mma.sync.aligned.m16n8k16.row.col.f32.f16.f16.f32 "
                        "{%0,%1,%2,%3}, {%4,%5,%6,%7}, {%8,%9}, {%0,%1,%2,%3};"
                        : "+f"(c[mt][nt][0]), "+f"(c[mt][nt][1]), "+f"(c[mt][nt][2]), "+f"(c[mt][nt][3])
                        : "r"(af[mt][0]), "r"(af[mt][1]), "r"(af[mt][2]), "r"(af[mt][3]),
                          "r"(bf[nt][0]), "r"(bf[nt][1]));
                }
        }
    }
}

// ---------------- B prep: g_bt[v][k] = fp16(out_w[k][v] + out_w[k+256][v]) ----------------
__global__ void __launch_bounds__(256) k_bsplit(const float* __restrict__ ow) {
    __shared__ float tile[32][33];
    int v0 = blockIdx.x * 32, k0 = blockIdx.y * 32;
    int tx = threadIdx.x & 31, ty = threadIdx.x >> 5;
    #pragma unroll
    for (int i = 0; i < 4; i++) {
        int k = k0 + ty + 8*i;
        tile[ty + 8*i][tx] = ow[(size_t)k*VV + v0 + tx] + ow[(size_t)(k + 256)*VV + v0 + tx];
    }
    __syncthreads();
    #pragma unroll
    for (int i = 0; i < 4; i++) {
        int v = v0 + ty + 8*i;
        g_bt[(size_t)v*DD + k0 + tx] = __float2half(tile[tx][ty + 8*i]);
    }
}

// ---------------- wmean for all layers ----------------
__global__ void k_wmean3(const float* __restrict__ W) {
    int l = blockIdx.x, t = threadIdx.x, lane = t & 31, w = t >> 5;
    for (int r = w; r < DD; r += 8) {
        const float* p = W + (size_t)l*DD*DD + (size_t)r*DD;
        float s = 0.f;
        #pragma unroll
        for (int j = 0; j < 8; j++) s += p[lane + 32*j];
        #pragma unroll
        for (int o = 16; o; o >>= 1) s += __shfl_xor_sync(0xffffffffu, s, o);
        if (lane == 0) g_wmean[l*DD + r] = s * (1.f/DD);
    }
}

// ---------------- embedding + phase space ----------------
__global__ void __launch_bounds__(256) k_phase(const int* __restrict__ x, const float* __restrict__ emb_real,
                        const float* __restrict__ lp, const float* __restrict__ iw,
                        const float* __restrict__ energy, const float* __restrict__ excf) {
    __shared__ float sh[16];
    int row = blockIdx.x, d = threadIdx.x;
    int tok = x[row];
    float re = emb_real[(size_t)tok*DD + d] * 0.1f;
    float fr = 0.f, fi = 0.f;
    const float cav[3] = {1.f, -0.5f, -0.5f};
    const float sav[3] = {0.f, 0.86602540378443865f, -0.86602540378443865f};
    const float PIPHI = 5.083203692315259f;
    #pragma unroll
    for (int i = 0; i < NLY; i++) {
        float pa = tanhf(lp[i*DD + d]) * PIPHI;
        float tr = re * cosf(pa);
        float ti = re * sinf(pa);
        float s1, s2;
        blockSum2(tr, tr*tr, sh, s1, s2);
        float mu = s1 * (1.f/DD);
        float r = (tr - mu) * rsqrtf(fmaxf(s2*(1.f/DD) - mu*mu, 0.f) + 1e-8f);
        blockSum2(ti, ti*ti, sh, s1, s2);
        mu = s1 * (1.f/DD);
        float im = (ti - mu) * rsqrtf(fmaxf(s2*(1.f/DD) - mu*mu, 0.f) + 1e-8f);
        float w = tanhf(iw[i*DD + d]);
        r *= w; im *= w;
        fr += r*cav[i] - im*sav[i];
        fi += r*sav[i] + im*cav[i];
    }
    float amp = sqrtf(fr*fr + fi*fi + 1e-8f);
    float exc = expf(energy[d]) * excf[0];
    if (amp < 0.1f) { fr += exc; fi += exc; }
    float nrm = rsqrtf(fr*fr + fi*fi + 1e-8f);
    g_real[row*DD + d] = clip1(fr * nrm);
    g_imag[row*DD + d] = clip1(fi * nrm);
}

// ---------------- layer 0 only: LN + operand staging ----------------
__global__ void __launch_bounds__(256) k_norm0() {
    __shared__ float sh[16];
    int row = blockIdx.x, d = threadIdx.x;
    int idx = row*DD + d;
    float r = g_real[idx];
    float s1, s2;
    blockSum2(r, r*r, sh, s1, s2);
    float mu = s1 * (1.f/DD);
    float nr = (r - mu) * rsqrtf(fmaxf(s2*(1.f/DD) - mu*mu, 0.f) + 1e-5f);
    float im = g_imag[idx];
    blockSum2(im, im*im, sh, s1, s2);
    mu = s1 * (1.f/DD);
    float ni = (im - mu) * rsqrtf(fmaxf(s2*(1.f/DD) - mu*mu, 0.f) + 1e-5f);
    float xx = nr + 1e-8f, yy = ni + 1e-8f;
    float h = rsqrtf(xx*xx + yy*yy);
    float cc = xx*h, ss = yy*h;
    g_c[idx] = cc; g_s[idx] = ss;
    float wm = g_wmean[d];
    g_cw[row*512 + d]       = __float2half(cc*wm);
    g_cw[row*512 + 256 + d] = __float2half(ss*wm);
    g_cs[row*512 + d]       = __float2half(cc);
    g_cs[row*512 + 256 + d] = __float2half(ss);
    g_nb[row*512 + d]       = __float2half(nr);
    g_nb[row*512 + 256 + d] = __float2half(ni);
}

// ---------------- per-layer: transpose g_nb -> g_nT (smem tiled) ----------------
__global__ void __launch_bounds__(256) k_trans() {
    __shared__ __half tl[32][33];
    int d0 = blockIdx.x*32, l0 = blockIdx.y*32, b = blockIdx.z;
    int tx = threadIdx.x & 31, ty = threadIdx.x >> 5;
    #pragma unroll
    for (int i = 0; i < 4; i++)
        tl[ty + 8*i][tx] = g_nb[(size_t)(b*LL + l0 + ty + 8*i)*512 + d0 + tx];
    __syncthreads();
    #pragma unroll
    for (int i = 0; i < 4; i++)
        g_nT[(size_t)b*512*LL + (size_t)(d0 + ty + 8*i)*LL + l0 + tx] = tl[tx][ty + 8*i];
}

// ---------------- per-layer: partial column sums for coherence ----------------
__global__ void k_colsum() {
    int b = blockIdx.x, ch = blockIdx.y, d = threadIdx.x;
    float sc = 0.f, ss = 0.f;
    #pragma unroll 4
    for (int m = ch*64; m < ch*64 + 64; m++) {
        int idx = (b*LL + m)*DD + d;
        sc += g_c[idx]; ss += g_s[idx];
    }
    g_scp[(b*6 + ch)*DD + d] = sc;
    g_ssp[(b*6 + ch)*DD + d] = ss;
}

// ---------------- per-layer: scores via 64x64 HMMA ----------------
__global__ void __launch_bounds__(128) k_scores_mma(const int* __restrict__ x) {
    __shared__ __align__(128) __half sA[2*64*32];
    __shared__ __align__(128) __half sB[2*64*32];
    int b = blockIdx.z, bm = blockIdx.y*64, bn = blockIdx.x*64;
    float c[2][4][4];
    #pragma unroll
    for (int i = 0; i < 2; i++)
        #pragma unroll
        for (int j = 0; j < 4; j++)
            #pragma unroll
            for (int q = 0; q < 4; q++) c[i][j][q] = 0.f;
    gemm_mainloop64(g_cw + (size_t)(b*LL + bm)*512, 512,
                    g_cs + (size_t)(b*LL + bn)*512, 512,
                    16, sA, sB, c);
    int lane = threadIdx.x & 31, wid = threadIdx.x >> 5;
    int wm = wid & 1, wn = wid >> 1;
    int rr0 = lane >> 2, cc0 = (lane & 3)*2;
    #pragma unroll
    for (int mt = 0; mt < 2; mt++)
        #pragma unroll
        for (int nt = 0; nt < 4; nt++) {
            int row = bm + wm*32 + mt*16 + rr0;
            int col = bn + wn*32 + nt*8 + cc0;
            bool p0 = (x[b*LL + col] == 0), p1 = (x[b*LL + col + 1] == 0);
            float2 o;
            o.x = p0 ? (-CUDART_INF_F) : c[mt][nt][0]*0.0625f;
            o.y = p1 ? (-CUDART_INF_F) : c[mt][nt][1]*0.0625f;
            *(float2*)&g_scores[(size_t)(b*LL + row)*LL + col] = o;
            o.x = p0 ? (-CUDART_INF_F) : c[mt][nt][2]*0.0625f;
            o.y = p1 ? (-CUDART_INF_F) : c[mt][nt][3]*0.0625f;
            *(float2*)&g_scores[(size_t)(b*LL + row + 8)*LL + col] = o;
        }
}

// ---------------- per-layer: softmax + clip -> fp16 attn ----------------
__global__ void k_softmax() {
    __shared__ float sh[128];
    int row = blockIdx.x, t = threadIdx.x;
    const float* sc = &g_scores[(size_t)row*LL];
    float v[3], mx = -CUDART_INF_F;
    #pragma unroll
    for (int r = 0; r < 3; r++) { v[r] = sc[t + 128*r]; mx = fmaxf(mx, v[r]); }
    sh[t] = mx; __syncthreads();
    #pragma unroll
    for (int s = 64; s > 0; s >>= 1) { if (t < s) sh[t] = fmaxf(sh[t], sh[t+s]); __syncthreads(); }
    mx = sh[0]; __syncthreads();
    float sum = 0.f;
    #pragma unroll
    for (int r = 0; r < 3; r++) { v[r] = expf(v[r] - mx); sum += v[r]; }
    sh[t] = sum; __syncthreads();
    #pragma unroll
    for (int s = 64; s > 0; s >>= 1) { if (t < s) sh[t] += sh[t+s]; __syncthreads(); }
    float inv = 1.f / sh[0];
    #pragma unroll
    for (int r = 0; r < 3; r++) {
        float p = fminf(fmaxf(v[r]*inv, 1e-6f), 1.f);
        g_attnb[(size_t)row*LL + t + 128*r] = __float2half(p);
    }
}

// ---------------- per-layer: out = attn @ [nr|ni]^T via 64x64 HMMA ----------------
__global__ void __launch_bounds__(128) k_out_mma() {
    __shared__ __align__(128) __half sA[2*64*32];
    __shared__ __align__(128) __half sB[2*64*32];
    int b = blockIdx.z, bm = blockIdx.y*64, bn = blockIdx.x*64;
    float c[2][4][4];
    #pragma unroll
    for (int i = 0; i < 2; i++)
        #pragma unroll
        for (int j = 0; j < 4; j++)
            #pragma unroll
            for (int q = 0; q < 4; q++) c[i][j][q] = 0.f;
    gemm_mainloop64(g_attnb + (size_t)(b*LL + bm)*LL, LL,
                    g_nT + (size_t)b*512*LL + (size_t)bn*LL, LL,
                    12, sA, sB, c);
    int lane = threadIdx.x & 31, wid = threadIdx.x >> 5;
    int wm = wid & 1, wn = wid >> 1;
    int rr0 = lane >> 2, cc0 = (lane & 3)*2;
    float* dst = (bn < 256) ? g_outr : g_outi;
    int nb = (bn < 256) ? bn : (bn - 256);
    #pragma unroll
    for (int mt = 0; mt < 2; mt++)
        #pragma unroll
        for (int nt = 0; nt < 4; nt++) {
            int row = bm + wm*32 + mt*16 + rr0;
            int col = nb + wn*32 + nt*8 + cc0;
            float2 o;
            o.x = c[mt][nt][0]; o.y = c[mt][nt][1];
            *(float2*)&dst[(size_t)(b*LL + row)*DD + col] = o;
            o.x = c[mt][nt][2]; o.y = c[mt][nt][3];
            *(float2*)&dst[(size_t)(b*LL + row + 8)*DD + col] = o;
        }
}

// ---------------- per-layer: coherence + residual LN, fused next-layer staging ----------------
__global__ void __launch_bounds__(256) k_update(const float* __restrict__ pp, const float* __restrict__ cohf,
                                                int layer, int last) {
    __shared__ float sh[16];
    int row = blockIdx.x, d = threadIdx.x;
    int b = row / LL;
    float SC = 0.f, SS = 0.f;
    #pragma unroll
    for (int ch = 0; ch < 6; ch++) {
        SC += g_scp[(b*6 + ch)*DD + d];
        SS += g_ssp[(b*6 + ch)*DD + d];
    }
    float part = g_c[row*DD + d]*SC + g_s[row*DD + d]*SS;
    float s1, s2;
    blockSum2(part, part, sh, s1, s2);
    float coh = s1 * (1.f / (float)(LL*DD));
    float cfv = sigm(cohf[layer]) * coh;
    float orv = g_outr[row*DD + d], oiv = g_outi[row*DD + d];
    float phase = atan2f(oiv + 1e-8f, orv + 1e-8f);
    float pres = sigm(pp[layer*DD + d]) * cfv;
    float pr = orv * cosf(phase * pres);
    float val = g_real[row*DD + d] + 0.01f * pr;
    blockSum2(val, val*val, sh, s1, s2);
    float mu = s1 * (1.f/DD);
    float r = clip1((val - mu) * rsqrtf(fmaxf(s2*(1.f/DD) - mu*mu, 0.f) + 1e-8f));
    if (!last) {
        g_real[row*DD + d] = r;
        blockSum2(r, r*r, sh, s1, s2);
        mu = s1 * (1.f/DD);
        float nr = (r - mu) * rsqrtf(fmaxf(s2*(1.f/DD) - mu*mu, 0.f) + 1e-5f);
        float ni = nr;
        float xx = nr + 1e-8f, yy = ni + 1e-8f;
        float h = rsqrtf(xx*xx + yy*yy);
        float cc = xx*h, ss = yy*h;
        int idx = row*DD + d;
        g_c[idx] = cc; g_s[idx] = ss;
        float wm = g_wmean[(layer + 1)*DD + d];
        g_cw[row*512 + d]       = __float2half(cc*wm);
        g_cw[row*512 + 256 + d] = __float2half(ss*wm);
        g_cs[row*512 + d]       = __float2half(cc);
        g_cs[row*512 + 256 + d] = __float2half(ss);
        g_nb[row*512 + d]       = __float2half(nr);
        g_nb[row*512 + 256 + d] = __float2half(ni);
    } else {
        // fused final LN + fp16 hi/lo split of A
        blockSum2(r, r*r, sh, s1, s2);
        mu = s1 * (1.f/DD);
        float a = (r - mu) * rsqrtf(fmaxf(s2*(1.f/DD) - mu*mu, 0.f) + 1e-5f);
        __half h = __float2half(a);
        __half l = __float2half(a - __half2float(h));
        size_t base = (size_t)row*KPA + d;
        g_aexp[base] = h;          // Ah
        g_aexp[base + 256] = l;    // Al
    }
}

// ---------------- final GEMM via fp16 HMMA: C[768,32000] ----------------
__global__ void __launch_bounds__(256) k_gemm_mma(const float* __restrict__ bias, float* __restrict__ out) {
    __shared__ __align__(128) __half sA[2*128*32];
    __shared__ __align__(128) __half sB[2*128*32];
    int bm = blockIdx.x * 128, bn = blockIdx.y * 128;
    float c[4][4][4];
    #pragma unroll
    for (int i = 0; i < 4; i++)
        #pragma unroll
        for (int j = 0; j < 4; j++)
            #pragma unroll
            for (int q = 0; q < 4; q++) c[i][j][q] = 0.f;
    gemm_mainloop(g_aexp + (size_t)bm*KPA, KPA,
                  g_bt + (size_t)bn*DD, DD,
                  16, g_tsplit, sA, sB, c);
    int lane = threadIdx.x & 31, wid = threadIdx.x >> 5;
    int wm = wid & 1, wn = wid >> 1;
    int rr0 = lane >> 2, cc0 = (lane & 3)*2;
    #pragma unroll
    for (int mt = 0; mt < 4; mt++) {
        #pragma unroll
        for (int nt = 0; nt < 4; nt++) {
            int row = bm + wm*64 + mt*16 + rr0;
            int col = bn + wn*32 + nt*8 + cc0;
            float b0 = bias[col], b1 = bias[col + 1];
            float2 o;
            o.x = fminf(fmaxf((c[mt][nt][0] + b0)*0.1f, -10.f), 10.f);
            o.y = fminf(fmaxf((c[mt][nt][1] + b1)*0.1f, -10.f), 10.f);
            *(float2*)&out[(size_t)row*VV + col] = o;
            o.x = fminf(fmaxf((c[mt][nt][2] + b0)*0.1f, -10.f), 10.f);
            o.y = fminf(fmaxf((c[mt][nt][3] + b1)*0.1f, -10.f), 10.f);
            *(float2*)&out[(size_t)(row + 8)*VV + col] = o;
        }
    }
}

// ---------------- launch ----------------
extern "C" void kernel_launch(void* const* d_in, const int* in_sizes, int n_in,
                              void* d_out, int out_size) {
    const int*   x        = (const int*)  d_in[0];
    const float* emb_real = (const float*)d_in[1];
    // d_in[2] = emb_imag: unused downstream (as in reference)
    const float* lp       = (const float*)d_in[3];
    const float* iw       = (const float*)d_in[4];
    const float* energy   = (const float*)d_in[5];
    const float* excf     = (const float*)d_in[6];
    const float* pp       = (const float*)d_in[7];
    const float* cohf     = (const float*)d_in[8];
    const float* Wattn    = (const float*)d_in[9];
    const float* out_w    = (const float*)d_in[10];
    const float* out_b    = (const float*)d_in[11];
    float* out = (float*)d_out;

    k_bsplit<<<dim3(VV/32, DD/32), 256>>>(out_w);
    k_wmean3<<<NLY, 256>>>(Wattn);
    k_phase<<<BL, 256>>>(x, emb_real, lp, iw, energy, excf);
    k_norm0<<<BL, 256>>>();
    for (int i = 0; i < NLY; i++) {
        k_trans<<<dim3(512/32, LL/32, BB), 256>>>();
        k_colsum<<<dim3(BB, 6), 256>>>();
        k_scores_mma<<<dim3(LL/64, LL/64, BB), 128>>>(x);
        k_softmax<<<BL, 128>>>();
        k_out_mma<<<dim3(512/64, LL/64, BB), 128>>>();
        k_update<<<BL, 256>>>(pp, cohf, i, i == NLY - 1 ? 1 : 0);
    }
    k_gemm_mma<<<dim3(BL/128, VV/128), 256>>>(out_b, out);
}